// round 9
// baseline (speedup 1.0000x reference)
#include <cuda_runtime.h>

#define ORDER 128
#define SEQN  16384
#define NB    64
#define LTAP  192
#define TILE  512
#define NTHR  128

// ---------------- scratch (device globals; no allocation) ----------------
__device__ double     g_P [2][ORDER * ORDER];      // ping-pong powers of A (fp64)
__device__ double     g_PT[2][ORDER * ORDER];      // transposes (for coalesced col access)
__device__ double     g_V[LTAP * ORDER * 7];       // V[j][r][c] = (A^j [B|x0])[r][c], c<7
__device__ ulonglong2 g_H2[LTAP * 9];              // packed fp32 taps per m (18 u64)
__device__ float      g_S[LTAP * 6];               // s_k = C A^k x0

// ---------------- precompute kernels (fp64, warp-coalesced) ----------------
__global__ void k_init(const float* __restrict__ A, const float* __restrict__ B,
                       const float* __restrict__ x0) {
    int t = blockIdx.x * blockDim.x + threadIdx.x;
    if (t < ORDER * ORDER) {
        int r = t >> 7, c = t & 127;
        double v = (double)A[t];
        g_P [0][t] = v;
        g_PT[0][c * ORDER + r] = v;
    }
    if (t < ORDER * 7) {
        int r = t / 7, c = t % 7;
        g_V[t] = (c < 6) ? (double)B[r * 6 + c] : (double)x0[r];
    }
}

// V[m + j] = P @ V[j] for j in [0, nj); if dosq: P' = P @ P (and its transpose)
__global__ void k_step(int m, int nj, int pi, int dosq) {
    const int w    = (blockIdx.x * blockDim.x + threadIdx.x) >> 5;
    const int lane = threadIdx.x & 31;
    const int Wv   = (nj <= 8) ? nj * ORDER : nj * 4;
    const int Wsq  = dosq ? 512 : 0;
    if (w >= Wv + Wsq) return;

    if (w < Wv) {
        const double* __restrict__ P  = g_P[pi];
        const double* __restrict__ PT = g_PT[pi];
        if (nj <= 8) {
            // warp per (j, r): lane = k, shfl reduce (low-latency for tiny nj)
            int j = w >> 7, r = w & 127;
            const double* Pr = P + r * ORDER;
            const double* Vj = g_V + j * (ORDER * 7);
            double acc[7] = {0, 0, 0, 0, 0, 0, 0};
            #pragma unroll
            for (int kk = 0; kk < 4; kk++) {
                int k = kk * 32 + lane;
                double a = Pr[k];
                const double* vk = Vj + k * 7;
                #pragma unroll
                for (int c = 0; c < 7; c++) acc[c] += a * vk[c];
            }
            #pragma unroll
            for (int off = 16; off; off >>= 1)
                #pragma unroll
                for (int c = 0; c < 7; c++)
                    acc[c] += __shfl_xor_sync(0xffffffffu, acc[c], off);
            if (lane == 0) {
                double* o = g_V + (m + j) * (ORDER * 7) + r * 7;
                #pragma unroll
                for (int c = 0; c < 7; c++) o[c] = acc[c];
            }
        } else {
            // warp per (j, 32-row group): lane = row, coalesced PT loads, no reduce
            int j = w >> 2, r = ((w & 3) << 5) + lane;
            const double* Vj = g_V + j * (ORDER * 7);
            double acc[7] = {0, 0, 0, 0, 0, 0, 0};
            #pragma unroll 4
            for (int k = 0; k < ORDER; k++) {
                double a = PT[k * ORDER + r];       // coalesced across lanes
                const double* vk = Vj + k * 7;      // uniform broadcast
                #pragma unroll
                for (int c = 0; c < 7; c++) acc[c] += a * vk[c];
            }
            double* o = g_V + (m + j) * (ORDER * 7) + r * 7;
            #pragma unroll
            for (int c = 0; c < 7; c++) o[c] = acc[c];
        }
    } else {
        // squaring: warp per (row r, col-quarter): lane = col, coalesced, no reduce
        int w2 = w - Wv;
        int r = w2 >> 2, c = ((w2 & 3) << 5) + lane;
        const double* __restrict__ P = g_P[pi];
        const double* Pr = P + r * ORDER;
        double acc = 0.0;
        #pragma unroll 8
        for (int k = 0; k < ORDER; k++)
            acc += Pr[k] * P[k * ORDER + c];        // broadcast * coalesced
        g_P [1 - pi][r * ORDER + c] = acc;
        g_PT[1 - pi][c * ORDER + r] = acc;
    }
}

// taps h_m (h_0 = D, h_m = C A^{m-1} B) in fp32 pair layout, plus s_k = C A^k x0
__global__ void k_taps(const float* __restrict__ C, const float* __restrict__ D) {
    const int NH = LTAP * 36;
    const int N  = NH + LTAP * 6;
    int tid = blockIdx.x * blockDim.x + threadIdx.x;
    if (tid >= N) return;
    float* Hf = (float*)g_H2;
    if (tid < NH) {
        int mm = tid / 36, r36 = tid % 36;
        int o = r36 / 6, i = r36 % 6;
        double v;
        if (mm == 0) {
            v = (double)D[o * 6 + i];
        } else {
            const double* vp = g_V + (mm - 1) * (ORDER * 7) + i;
            const float* cp = C + o * ORDER;
            v = 0.0;
            #pragma unroll 8
            for (int r = 0; r < ORDER; r++) v += (double)cp[r] * vp[r * 7];
        }
        // u64 index n = i*3 + (o>>1); float index = n*2 + (o&1)
        Hf[mm * 36 + ((i * 3 + (o >> 1)) * 2 + (o & 1))] = (float)v;
    } else {
        int t2 = tid - NH;
        int k = t2 / 6, o = t2 % 6;
        const float* cp = C + o * ORDER;
        const double* vp = g_V + k * (ORDER * 7) + 6;
        double v = 0.0;
        #pragma unroll 8
        for (int r = 0; r < ORDER; r++) v += (double)cp[r] * vp[r * 7];
        g_S[k * 6 + o] = (float)v;
    }
}

// ---------------- main convolution kernel (unchanged, FMA2-bound) ----------------
#define FMA2(acc, hh, uu) asm("fma.rn.f32x2 %0, %1, %2, %0;" : "+l"(acc) : "l"(hh), "l"(uu))
#define PACK2(d, f)  asm("mov.b64 %0, {%1, %1};" : "=l"(d) : "r"(__float_as_uint(f)))

__device__ __forceinline__ void unpk(unsigned long long v, float& a, float& b) {
    unsigned int lo, hi;
    asm("mov.b64 {%0, %1}, %2;" : "=r"(lo), "=r"(hi) : "l"(v));
    a = __uint_as_float(lo);
    b = __uint_as_float(hi);
}

#define LOADROW(Rn, p) do {                                   \
    PACK2(Rn##_0, (p)[0]); PACK2(Rn##_1, (p)[1]);             \
    PACK2(Rn##_2, (p)[2]); PACK2(Rn##_3, (p)[3]);             \
    PACK2(Rn##_4, (p)[4]); PACK2(Rn##_5, (p)[5]);             \
} while (0)

#define TAPI(h0, h1, h2, RA, RB, RC, RD, i) do {              \
    FMA2(a00, h0, RA##_##i); FMA2(a01, h1, RA##_##i); FMA2(a02, h2, RA##_##i); \
    FMA2(a10, h0, RB##_##i); FMA2(a11, h1, RB##_##i); FMA2(a12, h2, RB##_##i); \
    FMA2(a20, h0, RC##_##i); FMA2(a21, h1, RC##_##i); FMA2(a22, h2, RC##_##i); \
    FMA2(a30, h0, RD##_##i); FMA2(a31, h1, RD##_##i); FMA2(a32, h2, RD##_##i); \
} while (0)

#define STEP(hp, RA, RB, RC, RD) do {                         \
    ulonglong2 t0 = (hp)[0], t1 = (hp)[1], t2 = (hp)[2];      \
    TAPI(t0.x, t0.y, t1.x, RA, RB, RC, RD, 0);                \
    TAPI(t1.y, t2.x, t2.y, RA, RB, RC, RD, 1);                \
    ulonglong2 t3 = (hp)[3], t4 = (hp)[4], t5 = (hp)[5];      \
    TAPI(t3.x, t3.y, t4.x, RA, RB, RC, RD, 2);                \
    TAPI(t4.y, t5.x, t5.y, RA, RB, RC, RD, 3);                \
    ulonglong2 t6 = (hp)[6], t7 = (hp)[7], t8 = (hp)[8];      \
    TAPI(t6.x, t6.y, t7.x, RA, RB, RC, RD, 4);                \
    TAPI(t7.y, t8.x, t8.y, RA, RB, RC, RD, 5);                \
} while (0)

__global__ void __launch_bounds__(NTHR, 3) k_conv(
    const float* __restrict__ u,
    const float* __restrict__ imean, const float* __restrict__ istd,
    const float* __restrict__ omean, const float* __restrict__ ostd,
    float* __restrict__ out)
{
    __shared__ float      su[(TILE + LTAP) * 7];   // stride 7 (conflict padding)
    __shared__ ulonglong2 sh[LTAP * 9];            // packed taps

    const int tid = threadIdx.x;
    const int b  = blockIdx.y;
    const int k0 = blockIdx.x * TILE;

    for (int idx = tid; idx < LTAP * 9; idx += NTHR) sh[idx] = g_H2[idx];

    float im[6], rs[6];
    #pragma unroll
    for (int i = 0; i < 6; i++) { im[i] = imean[i]; rs[i] = 1.0f / istd[i]; }
    const float* ub = u + ((long long)b * SEQN) * 6;
    for (int idx = tid; idx < (TILE + LTAP) * 6; idx += NTHR) {
        int sr = idx / 6, i = idx - sr * 6;
        int k = k0 - LTAP + sr;
        float v = 0.f;
        if (k >= 0) v = (ub[k * 6 + i] - im[i]) * rs[i];
        su[sr * 7 + i] = v;
    }
    __syncthreads();

    const int kb = tid * 4;
    const float* up = su + (kb + LTAP) * 7;

    unsigned long long r0_0, r0_1, r0_2, r0_3, r0_4, r0_5;
    unsigned long long r1_0, r1_1, r1_2, r1_3, r1_4, r1_5;
    unsigned long long r2_0, r2_1, r2_2, r2_3, r2_4, r2_5;
    unsigned long long r3_0, r3_1, r3_2, r3_3, r3_4, r3_5;
    unsigned long long a00 = 0, a01 = 0, a02 = 0, a10 = 0, a11 = 0, a12 = 0;
    unsigned long long a20 = 0, a21 = 0, a22 = 0, a30 = 0, a31 = 0, a32 = 0;

    LOADROW(r0, up);
    LOADROW(r1, up + 7);
    LOADROW(r2, up + 14);
    LOADROW(r3, up + 21);

    const ulonglong2* hpp = sh;
    #pragma unroll 1
    for (int it = 0; it < LTAP / 4; ++it) {
        STEP(hpp,      r0, r1, r2, r3);  LOADROW(r3, up - 7);
        STEP(hpp + 9,  r3, r0, r1, r2);  LOADROW(r2, up - 14);
        STEP(hpp + 18, r2, r3, r0, r1);  LOADROW(r1, up - 21);
        STEP(hpp + 27, r1, r2, r3, r0);  LOADROW(r0, up - 28);
        hpp += 36;
        up  -= 28;
    }

    // ---------------- epilogue ----------------
    const float os0 = ostd[0], os1 = ostd[1], os2 = ostd[2];
    const float os3 = ostd[3], os4 = ostd[4], os5 = ostd[5];
    const float om0 = omean[0], om1 = omean[1], om2 = omean[2];
    const float om3 = omean[3], om4 = omean[4], om5 = omean[5];
    const bool addinit = (k0 == 0);
    float* outp = out + ((long long)b * SEQN + (k0 + kb)) * 6;

#define EPI(j, A0, A1, A2) do {                                               \
    float y0, y1, y2, y3, y4, y5;                                             \
    unpk(A0, y0, y1); unpk(A1, y2, y3); unpk(A2, y4, y5);                     \
    if (addinit) {                                                            \
        int kk = kb + (j);                                                    \
        if (kk < LTAP) {                                                      \
            const float* sp = g_S + kk * 6;                                   \
            y0 += sp[0]; y1 += sp[1]; y2 += sp[2];                            \
            y3 += sp[3]; y4 += sp[4]; y5 += sp[5];                            \
        }                                                                     \
    }                                                                         \
    float* op = outp + (j) * 6;                                               \
    op[0] = fmaf(y0, os0, om0); op[1] = fmaf(y1, os1, om1);                   \
    op[2] = fmaf(y2, os2, om2); op[3] = fmaf(y3, os3, om3);                   \
    op[4] = fmaf(y4, os4, om4); op[5] = fmaf(y5, os5, om5);                   \
} while (0)

    EPI(0, a00, a01, a02);
    EPI(1, a10, a11, a12);
    EPI(2, a20, a21, a22);
    EPI(3, a30, a31, a32);
#undef EPI
}

// ---------------- launch ----------------
extern "C" void kernel_launch(void* const* d_in, const int* in_sizes, int n_in,
                              void* d_out, int out_size) {
    const float* inp   = (const float*)d_in[0];
    const float* A     = (const float*)d_in[1];
    const float* B     = (const float*)d_in[2];
    const float* C     = (const float*)d_in[3];
    const float* D     = (const float*)d_in[4];
    const float* x0    = (const float*)d_in[5];
    const float* imean = (const float*)d_in[6];
    const float* istd  = (const float*)d_in[7];
    const float* omean = (const float*)d_in[8];
    const float* ostd  = (const float*)d_in[9];
    float* out = (float*)d_out;

    k_init<<<64, 256>>>(A, B, x0);

    const int ms[8]  = {1, 2, 4, 8, 16, 32, 64, 128};
    const int njs[8] = {1, 2, 4, 8, 16, 32, 64, 64};
    int pi = 0;
    for (int s = 0; s < 8; s++) {
        int dosq = (s < 7) ? 1 : 0;
        int nj = njs[s];
        int Wv = (nj <= 8) ? nj * ORDER : nj * 4;
        int W  = Wv + (dosq ? 512 : 0);
        int threads = W * 32;
        k_step<<<(threads + 255) / 256, 256>>>(ms[s], nj, pi, dosq);
        if (dosq) pi ^= 1;
    }

    k_taps<<<(LTAP * 42 + 255) / 256, 256>>>(C, D);

    dim3 grid(SEQN / TILE, NB);
    k_conv<<<grid, NTHR>>>(inp, imean, istd, omean, ostd, out);
}

// round 11
// speedup vs baseline: 1.4329x; 1.4329x over previous
#include <cuda_runtime.h>

#define ORDER 128
#define SEQN  16384
#define NB    64
#define LTAP  192
#define TILE  512
#define NTHR  128

// ---------------- scratch (device globals; no allocation) ----------------
__device__ float      g_P [2][ORDER * ORDER];      // ping-pong powers of A
__device__ float      g_PT[2][ORDER * ORDER];      // transposes (coalesced col access)
__device__ float      g_V[LTAP * ORDER * 7];       // V[j][r][c] = (A^j [B|x0])[r][c], c<7
__device__ ulonglong2 g_H2[LTAP * 9];              // packed fp32 taps per m (18 u64)
__device__ float      g_S[LTAP * 6];               // s_k = C A^k x0

// ---------------- precompute kernels (fp32, warp-coalesced) ----------------
__global__ void k_init(const float* __restrict__ A, const float* __restrict__ B,
                       const float* __restrict__ x0) {
    int t = blockIdx.x * blockDim.x + threadIdx.x;
    if (t < ORDER * ORDER) {
        int r = t >> 7, c = t & 127;
        float v = A[t];
        g_P [0][t] = v;
        g_PT[0][c * ORDER + r] = v;
    }
    if (t < ORDER * 7) {
        int r = t / 7, c = t % 7;
        g_V[t] = (c < 6) ? B[r * 6 + c] : x0[r];
    }
}

// V[m + j] = P @ V[j] for j in [0, nj); if dosq: P' = P @ P (and transpose)
__global__ void k_step(int m, int nj, int pi, int dosq) {
    const int w    = (blockIdx.x * blockDim.x + threadIdx.x) >> 5;
    const int lane = threadIdx.x & 31;
    const int Wv   = (nj <= 8) ? nj * ORDER : nj * 4;
    const int Wsq  = dosq ? 512 : 0;
    if (w >= Wv + Wsq) return;

    if (w < Wv) {
        const float* __restrict__ P  = g_P[pi];
        const float* __restrict__ PT = g_PT[pi];
        if (nj <= 8) {
            // warp per (j, r): lane = k, shfl reduce (low-latency for tiny nj)
            int j = w >> 7, r = w & 127;
            const float* Pr = P + r * ORDER;
            const float* Vj = g_V + j * (ORDER * 7);
            float acc[7] = {0, 0, 0, 0, 0, 0, 0};
            #pragma unroll
            for (int kk = 0; kk < 4; kk++) {
                int k = kk * 32 + lane;
                float a = Pr[k];
                const float* vk = Vj + k * 7;
                #pragma unroll
                for (int c = 0; c < 7; c++) acc[c] += a * vk[c];
            }
            #pragma unroll
            for (int off = 16; off; off >>= 1)
                #pragma unroll
                for (int c = 0; c < 7; c++)
                    acc[c] += __shfl_xor_sync(0xffffffffu, acc[c], off);
            if (lane == 0) {
                float* o = g_V + (m + j) * (ORDER * 7) + r * 7;
                #pragma unroll
                for (int c = 0; c < 7; c++) o[c] = acc[c];
            }
        } else {
            // warp per (j, 32-row group): lane = row, coalesced PT loads, no reduce
            int j = w >> 2, r = ((w & 3) << 5) + lane;
            const float* Vj = g_V + j * (ORDER * 7);
            float acc[7] = {0, 0, 0, 0, 0, 0, 0};
            #pragma unroll 4
            for (int k = 0; k < ORDER; k++) {
                float a = PT[k * ORDER + r];        // coalesced across lanes
                const float* vk = Vj + k * 7;       // uniform broadcast
                #pragma unroll
                for (int c = 0; c < 7; c++) acc[c] += a * vk[c];
            }
            float* o = g_V + (m + j) * (ORDER * 7) + r * 7;
            #pragma unroll
            for (int c = 0; c < 7; c++) o[c] = acc[c];
        }
    } else {
        // squaring: warp per (row r, col-quarter): lane = col, coalesced
        int w2 = w - Wv;
        int r = w2 >> 2, c = ((w2 & 3) << 5) + lane;
        const float* __restrict__ P = g_P[pi];
        const float* Pr = P + r * ORDER;
        float a0 = 0.f, a1 = 0.f, a2 = 0.f, a3 = 0.f;   // break FFMA dep chain
        #pragma unroll 4
        for (int k = 0; k < ORDER; k += 4) {
            a0 += Pr[k + 0] * P[(k + 0) * ORDER + c];
            a1 += Pr[k + 1] * P[(k + 1) * ORDER + c];
            a2 += Pr[k + 2] * P[(k + 2) * ORDER + c];
            a3 += Pr[k + 3] * P[(k + 3) * ORDER + c];
        }
        float acc = (a0 + a1) + (a2 + a3);
        g_P [1 - pi][r * ORDER + c] = acc;
        g_PT[1 - pi][c * ORDER + r] = acc;
    }
}

// taps h_m (h_0 = D, h_m = C A^{m-1} B) in pair layout, plus s_k = C A^k x0
__global__ void k_taps(const float* __restrict__ C, const float* __restrict__ D) {
    const int NH = LTAP * 36;
    const int N  = NH + LTAP * 6;
    int tid = blockIdx.x * blockDim.x + threadIdx.x;
    if (tid >= N) return;
    float* Hf = (float*)g_H2;
    if (tid < NH) {
        int mm = tid / 36, r36 = tid % 36;
        int o = r36 / 6, i = r36 % 6;
        float v;
        if (mm == 0) {
            v = D[o * 6 + i];
        } else {
            const float* vp = g_V + (mm - 1) * (ORDER * 7) + i;
            const float* cp = C + o * ORDER;
            v = 0.f;
            #pragma unroll 8
            for (int r = 0; r < ORDER; r++) v += cp[r] * vp[r * 7];
        }
        // u64 index n = i*3 + (o>>1); float index = n*2 + (o&1)
        Hf[mm * 36 + ((i * 3 + (o >> 1)) * 2 + (o & 1))] = v;
    } else {
        int t2 = tid - NH;
        int k = t2 / 6, o = t2 % 6;
        const float* cp = C + o * ORDER;
        const float* vp = g_V + k * (ORDER * 7) + 6;
        float v = 0.f;
        #pragma unroll 8
        for (int r = 0; r < ORDER; r++) v += cp[r] * vp[r * 7];
        g_S[k * 6 + o] = v;
    }
}

// ---------------- main convolution kernel (FMA2-pipe-bound) ----------------
#define FMA2(acc, hh, uu) asm("fma.rn.f32x2 %0, %1, %2, %0;" : "+l"(acc) : "l"(hh), "l"(uu))
#define PACK2(d, f)  asm("mov.b64 %0, {%1, %1};" : "=l"(d) : "r"(__float_as_uint(f)))

__device__ __forceinline__ void unpk(unsigned long long v, float& a, float& b) {
    unsigned int lo, hi;
    asm("mov.b64 {%0, %1}, %2;" : "=r"(lo), "=r"(hi) : "l"(v));
    a = __uint_as_float(lo);
    b = __uint_as_float(hi);
}

#define LOADROW(Rn, p) do {                                   \
    PACK2(Rn##_0, (p)[0]); PACK2(Rn##_1, (p)[1]);             \
    PACK2(Rn##_2, (p)[2]); PACK2(Rn##_3, (p)[3]);             \
    PACK2(Rn##_4, (p)[4]); PACK2(Rn##_5, (p)[5]);             \
} while (0)

#define TAPI(h0, h1, h2, RA, RB, RC, RD, i) do {              \
    FMA2(a00, h0, RA##_##i); FMA2(a01, h1, RA##_##i); FMA2(a02, h2, RA##_##i); \
    FMA2(a10, h0, RB##_##i); FMA2(a11, h1, RB##_##i); FMA2(a12, h2, RB##_##i); \
    FMA2(a20, h0, RC##_##i); FMA2(a21, h1, RC##_##i); FMA2(a22, h2, RC##_##i); \
    FMA2(a30, h0, RD##_##i); FMA2(a31, h1, RD##_##i); FMA2(a32, h2, RD##_##i); \
} while (0)

#define STEP(hp, RA, RB, RC, RD) do {                         \
    ulonglong2 t0 = (hp)[0], t1 = (hp)[1], t2 = (hp)[2];      \
    TAPI(t0.x, t0.y, t1.x, RA, RB, RC, RD, 0);                \
    TAPI(t1.y, t2.x, t2.y, RA, RB, RC, RD, 1);                \
    ulonglong2 t3 = (hp)[3], t4 = (hp)[4], t5 = (hp)[5];      \
    TAPI(t3.x, t3.y, t4.x, RA, RB, RC, RD, 2);                \
    TAPI(t4.y, t5.x, t5.y, RA, RB, RC, RD, 3);                \
    ulonglong2 t6 = (hp)[6], t7 = (hp)[7], t8 = (hp)[8];      \
    TAPI(t6.x, t6.y, t7.x, RA, RB, RC, RD, 4);                \
    TAPI(t7.y, t8.x, t8.y, RA, RB, RC, RD, 5);                \
} while (0)

__global__ void __launch_bounds__(NTHR, 3) k_conv(
    const float* __restrict__ u,
    const float* __restrict__ imean, const float* __restrict__ istd,
    const float* __restrict__ omean, const float* __restrict__ ostd,
    float* __restrict__ out)
{
    __shared__ float      su[(TILE + LTAP) * 7];   // stride 7 (conflict padding)
    __shared__ ulonglong2 sh[LTAP * 9];            // packed taps (27.6 KB)

    const int tid = threadIdx.x;
    const int b  = blockIdx.y;
    const int k0 = blockIdx.x * TILE;

    for (int idx = tid; idx < LTAP * 9; idx += NTHR) sh[idx] = g_H2[idx];

    float im[6], rs[6];
    #pragma unroll
    for (int i = 0; i < 6; i++) { im[i] = imean[i]; rs[i] = 1.0f / istd[i]; }
    const float* ub = u + ((long long)b * SEQN) * 6;
    for (int idx = tid; idx < (TILE + LTAP) * 6; idx += NTHR) {
        int sr = idx / 6, i = idx - sr * 6;
        int k = k0 - LTAP + sr;
        float v = 0.f;
        if (k >= 0) v = (ub[k * 6 + i] - im[i]) * rs[i];
        su[sr * 7 + i] = v;
    }
    __syncthreads();

    const int kb = tid * 4;
    const float* up = su + (kb + LTAP) * 7;

    unsigned long long r0_0, r0_1, r0_2, r0_3, r0_4, r0_5;
    unsigned long long r1_0, r1_1, r1_2, r1_3, r1_4, r1_5;
    unsigned long long r2_0, r2_1, r2_2, r2_3, r2_4, r2_5;
    unsigned long long r3_0, r3_1, r3_2, r3_3, r3_4, r3_5;
    unsigned long long a00 = 0, a01 = 0, a02 = 0, a10 = 0, a11 = 0, a12 = 0;
    unsigned long long a20 = 0, a21 = 0, a22 = 0, a30 = 0, a31 = 0, a32 = 0;

    LOADROW(r0, up);
    LOADROW(r1, up + 7);
    LOADROW(r2, up + 14);
    LOADROW(r3, up + 21);

    const ulonglong2* hpp = sh;
    #pragma unroll 1
    for (int it = 0; it < LTAP / 4; ++it) {
        STEP(hpp,      r0, r1, r2, r3);  LOADROW(r3, up - 7);
        STEP(hpp + 9,  r3, r0, r1, r2);  LOADROW(r2, up - 14);
        STEP(hpp + 18, r2, r3, r0, r1);  LOADROW(r1, up - 21);
        STEP(hpp + 27, r1, r2, r3, r0);  LOADROW(r0, up - 28);
        hpp += 36;
        up  -= 28;
    }

    // ---------------- epilogue ----------------
    const float os0 = ostd[0], os1 = ostd[1], os2 = ostd[2];
    const float os3 = ostd[3], os4 = ostd[4], os5 = ostd[5];
    const float om0 = omean[0], om1 = omean[1], om2 = omean[2];
    const float om3 = omean[3], om4 = omean[4], om5 = omean[5];
    const bool addinit = (k0 == 0);
    float* outp = out + ((long long)b * SEQN + (k0 + kb)) * 6;

#define EPI(j, A0, A1, A2) do {                                               \
    float y0, y1, y2, y3, y4, y5;                                             \
    unpk(A0, y0, y1); unpk(A1, y2, y3); unpk(A2, y4, y5);                     \
    if (addinit) {                                                            \
        int kk = kb + (j);                                                    \
        if (kk < LTAP) {                                                      \
            const float* sp = g_S + kk * 6;                                   \
            y0 += sp[0]; y1 += sp[1]; y2 += sp[2];                            \
            y3 += sp[3]; y4 += sp[4]; y5 += sp[5];                            \
        }                                                                     \
    }                                                                         \
    float* op = outp + (j) * 6;                                               \
    op[0] = fmaf(y0, os0, om0); op[1] = fmaf(y1, os1, om1);                   \
    op[2] = fmaf(y2, os2, om2); op[3] = fmaf(y3, os3, om3);                   \
    op[4] = fmaf(y4, os4, om4); op[5] = fmaf(y5, os5, om5);                   \
} while (0)

    EPI(0, a00, a01, a02);
    EPI(1, a10, a11, a12);
    EPI(2, a20, a21, a22);
    EPI(3, a30, a31, a32);
#undef EPI
}

// ---------------- launch ----------------
extern "C" void kernel_launch(void* const* d_in, const int* in_sizes, int n_in,
                              void* d_out, int out_size) {
    const float* inp   = (const float*)d_in[0];
    const float* A     = (const float*)d_in[1];
    const float* B     = (const float*)d_in[2];
    const float* C     = (const float*)d_in[3];
    const float* D     = (const float*)d_in[4];
    const float* x0    = (const float*)d_in[5];
    const float* imean = (const float*)d_in[6];
    const float* istd  = (const float*)d_in[7];
    const float* omean = (const float*)d_in[8];
    const float* ostd  = (const float*)d_in[9];
    float* out = (float*)d_out;

    k_init<<<64, 256>>>(A, B, x0);

    // powers: m = 1,2,4,...,128 (8 launches) to cover j < 192
    const int ms[8]  = {1, 2, 4, 8, 16, 32, 64, 128};
    const int njs[8] = {1, 2, 4, 8, 16, 32, 64, 64};
    int pi = 0;
    for (int s = 0; s < 8; s++) {
        int dosq = (s < 7) ? 1 : 0;
        int nj = njs[s];
        int Wv = (nj <= 8) ? nj * ORDER : nj * 4;
        int W  = Wv + (dosq ? 512 : 0);
        int threads = W * 32;
        k_step<<<(threads + 255) / 256, 256>>>(ms[s], nj, pi, dosq);
        if (dosq) pi ^= 1;
    }

    k_taps<<<(LTAP * 42 + 255) / 256, 256>>>(C, D);

    dim3 grid(SEQN / TILE, NB);
    k_conv<<<grid, NTHR>>>(inp, imean, istd, omean, ostd, out);
}

// round 13
// speedup vs baseline: 1.7089x; 1.1926x over previous
#include <cuda_runtime.h>

#define ORDER 128
#define SEQN  16384
#define NB    64
#define LTAP  192
#define TILE  512
#define NTHR  128
#define SUBLEN  ((TILE + LTAP) / 4)     // 176 rows per subarray
#define SUBSTR  (SUBLEN * 7)            // 1232 floats

// ---------------- scratch (device globals; no allocation) ----------------
__device__ float      g_P [2][ORDER * ORDER];      // ping-pong powers of A
__device__ float      g_PT[2][ORDER * ORDER];      // transposes (coalesced col access)
__device__ float      g_V[LTAP * ORDER * 7];       // V[j][r][c] = (A^j [B|x0])[r][c], c<7
__device__ ulonglong2 g_H2[LTAP * 9];              // packed fp32 taps per m (18 u64)
__device__ float      g_S[LTAP * 6];               // s_k = C A^k x0

// ---------------- precompute ----------------
__global__ void k_init(const float* __restrict__ A, const float* __restrict__ B,
                       const float* __restrict__ x0) {
    int t = blockIdx.x * blockDim.x + threadIdx.x;
    if (t < ORDER * ORDER) {
        int r = t >> 7, c = t & 127;
        float v = A[t];
        g_P [0][t] = v;
        g_PT[0][c * ORDER + r] = v;
    }
    if (t < ORDER * 7) {
        int r = t / 7, c = t % 7;
        g_V[t] = (c < 6) ? B[r * 6 + c] : x0[r];
    }
}

// blocks [0, nj): V[m + j0 + b] = P @ V[j0 + b]   (block-per-j, 128 threads)
// blocks [nj, nj+128) if dosq: row r = b - nj of P' = P @ P (and transpose)
__global__ void k_step2(int m, int j0, int nj, int pi, int dosq) {
    const int tid = threadIdx.x;
    if ((int)blockIdx.x < nj) {
        const int j = j0 + blockIdx.x;
        __shared__ float vj[ORDER * 7];
        for (int idx = tid; idx < ORDER * 7; idx += 128)
            vj[idx] = g_V[j * (ORDER * 7) + idx];
        __syncthreads();
        const float* __restrict__ PT = g_PT[pi];
        const int r = tid;
        float acc[7] = {0, 0, 0, 0, 0, 0, 0};
        #pragma unroll 8
        for (int k = 0; k < ORDER; k++) {
            float a = PT[k * ORDER + r];           // coalesced across threads
            const float* vk = vj + k * 7;          // smem broadcast
            #pragma unroll
            for (int c = 0; c < 7; c++) acc[c] += a * vk[c];
        }
        float* o = g_V + (m + j) * (ORDER * 7) + r * 7;
        #pragma unroll
        for (int c = 0; c < 7; c++) o[c] = acc[c];
    } else {
        const int r = blockIdx.x - nj;             // squaring row
        const int c = tid;
        const float* __restrict__ P = g_P[pi];
        const float* Pr = P + r * ORDER;
        float a0 = 0.f, a1 = 0.f, a2 = 0.f, a3 = 0.f;
        #pragma unroll 4
        for (int k = 0; k < ORDER; k += 4) {
            a0 += Pr[k + 0] * P[(k + 0) * ORDER + c];   // broadcast * coalesced
            a1 += Pr[k + 1] * P[(k + 1) * ORDER + c];
            a2 += Pr[k + 2] * P[(k + 2) * ORDER + c];
            a3 += Pr[k + 3] * P[(k + 3) * ORDER + c];
        }
        float acc = (a0 + a1) + (a2 + a3);
        g_P [1 - pi][r * ORDER + c] = acc;
        g_PT[1 - pi][c * ORDER + r] = acc;
    }
}

// taps h_m (h_0 = D, h_m = C A^{m-1} B) in pair layout, plus s_k = C A^k x0
__global__ void k_taps(const float* __restrict__ C, const float* __restrict__ D) {
    const int NH = LTAP * 36;
    const int N  = NH + LTAP * 6;
    int tid = blockIdx.x * blockDim.x + threadIdx.x;
    if (tid >= N) return;
    float* Hf = (float*)g_H2;
    if (tid < NH) {
        int mm = tid / 36, r36 = tid % 36;
        int o = r36 / 6, i = r36 % 6;
        float v;
        if (mm == 0) {
            v = D[o * 6 + i];
        } else {
            const float* vp = g_V + (mm - 1) * (ORDER * 7) + i;
            const float* cp = C + o * ORDER;
            v = 0.f;
            #pragma unroll 8
            for (int r = 0; r < ORDER; r++) v += cp[r] * vp[r * 7];
        }
        Hf[mm * 36 + ((i * 3 + (o >> 1)) * 2 + (o & 1))] = v;
    } else {
        int t2 = tid - NH;
        int k = t2 / 6, o = t2 % 6;
        const float* cp = C + o * ORDER;
        const float* vp = g_V + k * (ORDER * 7) + 6;
        float v = 0.f;
        #pragma unroll 8
        for (int r = 0; r < ORDER; r++) v += cp[r] * vp[r * 7];
        g_S[k * 6 + o] = v;
    }
}

// ---------------- main convolution kernel (FMA2-pipe-bound) ----------------
#define FMA2(acc, hh, uu) asm("fma.rn.f32x2 %0, %1, %2, %0;" : "+l"(acc) : "l"(hh), "l"(uu))
#define PACK2(d, f)  asm("mov.b64 %0, {%1, %1};" : "=l"(d) : "r"(__float_as_uint(f)))

__device__ __forceinline__ void unpk(unsigned long long v, float& a, float& b) {
    unsigned int lo, hi;
    asm("mov.b64 {%0, %1}, %2;" : "=r"(lo), "=r"(hi) : "l"(v));
    a = __uint_as_float(lo);
    b = __uint_as_float(hi);
}

#define LOADROW(Rn, p) do {                                   \
    PACK2(Rn##_0, (p)[0]); PACK2(Rn##_1, (p)[1]);             \
    PACK2(Rn##_2, (p)[2]); PACK2(Rn##_3, (p)[3]);             \
    PACK2(Rn##_4, (p)[4]); PACK2(Rn##_5, (p)[5]);             \
} while (0)

#define TAPI(h0, h1, h2, RA, RB, RC, RD, i) do {              \
    FMA2(a00, h0, RA##_##i); FMA2(a01, h1, RA##_##i); FMA2(a02, h2, RA##_##i); \
    FMA2(a10, h0, RB##_##i); FMA2(a11, h1, RB##_##i); FMA2(a12, h2, RB##_##i); \
    FMA2(a20, h0, RC##_##i); FMA2(a21, h1, RC##_##i); FMA2(a22, h2, RC##_##i); \
    FMA2(a30, h0, RD##_##i); FMA2(a31, h1, RD##_##i); FMA2(a32, h2, RD##_##i); \
} while (0)

#define STEP(hp, RA, RB, RC, RD) do {                         \
    ulonglong2 t0 = (hp)[0], t1 = (hp)[1], t2 = (hp)[2];      \
    TAPI(t0.x, t0.y, t1.x, RA, RB, RC, RD, 0);                \
    TAPI(t1.y, t2.x, t2.y, RA, RB, RC, RD, 1);                \
    ulonglong2 t3 = (hp)[3], t4 = (hp)[4], t5 = (hp)[5];      \
    TAPI(t3.x, t3.y, t4.x, RA, RB, RC, RD, 2);                \
    TAPI(t4.y, t5.x, t5.y, RA, RB, RC, RD, 3);                \
    ulonglong2 t6 = (hp)[6], t7 = (hp)[7], t8 = (hp)[8];      \
    TAPI(t6.x, t6.y, t7.x, RA, RB, RC, RD, 4);                \
    TAPI(t7.y, t8.x, t8.y, RA, RB, RC, RD, 5);                \
} while (0)

__global__ void __launch_bounds__(NTHR, 3) k_conv(
    const float* __restrict__ u,
    const float* __restrict__ imean, const float* __restrict__ istd,
    const float* __restrict__ omean, const float* __restrict__ ostd,
    float* __restrict__ out)
{
    // 4 subarrays by (row & 3): at any tap, lanes hit ONE subarray at
    // idx = lane + const, stride 7 -> gcd(7,32)=1 -> conflict-free.
    __shared__ float      su[4 * SUBSTR];
    __shared__ ulonglong2 sh[LTAP * 9];            // packed taps (27.6 KB)

    const int tid = threadIdx.x;
    const int b  = blockIdx.y;
    const int k0 = blockIdx.x * TILE;

    for (int idx = tid; idx < LTAP * 9; idx += NTHR) sh[idx] = g_H2[idx];

    float im[6], rs[6];
    #pragma unroll
    for (int i = 0; i < 6; i++) { im[i] = imean[i]; rs[i] = 1.0f / istd[i]; }
    const float* ub = u + ((long long)b * SEQN) * 6;
    for (int idx = tid; idx < (TILE + LTAP) * 6; idx += NTHR) {
        int sr = idx / 6, i = idx - sr * 6;
        int k = k0 - LTAP + sr;
        float v = 0.f;
        if (k >= 0) v = (ub[k * 6 + i] - im[i]) * rs[i];
        su[(sr & 3) * SUBSTR + (sr >> 2) * 7 + i] = v;
    }
    __syncthreads();

    const int kb = tid * 4;                       // this thread's 4 outputs
    // local row of output k (tap 0): lr0 = kb + LTAP = 4*tid + 192 (≡ 0 mod 4)
    const int idx0 = tid + (LTAP >> 2);           // (lr0 >> 2)
    const float* p0 = su + 0 * SUBSTR + idx0 * 7; // rows ≡ 0 (incl. row k)
    const float* p1 = su + 1 * SUBSTR + idx0 * 7; // rows ≡ 1 (incl. row k+1)
    const float* p2 = su + 2 * SUBSTR + idx0 * 7;
    const float* p3 = su + 3 * SUBSTR + idx0 * 7;

    unsigned long long r0_0, r0_1, r0_2, r0_3, r0_4, r0_5;
    unsigned long long r1_0, r1_1, r1_2, r1_3, r1_4, r1_5;
    unsigned long long r2_0, r2_1, r2_2, r2_3, r2_4, r2_5;
    unsigned long long r3_0, r3_1, r3_2, r3_3, r3_4, r3_5;
    unsigned long long a00 = 0, a01 = 0, a02 = 0, a10 = 0, a11 = 0, a12 = 0;
    unsigned long long a20 = 0, a21 = 0, a22 = 0, a30 = 0, a31 = 0, a32 = 0;

    LOADROW(r0, p0);          // row k
    LOADROW(r1, p1);          // row k+1
    LOADROW(r2, p2);          // row k+2
    LOADROW(r3, p3);          // row k+3

    const ulonglong2* hpp = sh;
    #pragma unroll 1
    for (int it = 0; it < LTAP / 4; ++it) {
        STEP(hpp,      r0, r1, r2, r3);  p3 -= 7; LOADROW(r3, p3);  // row k-1-4it
        STEP(hpp + 9,  r3, r0, r1, r2);  p2 -= 7; LOADROW(r2, p2);  // row k-2-4it
        STEP(hpp + 18, r2, r3, r0, r1);  p1 -= 7; LOADROW(r1, p1);  // row k-3-4it
        STEP(hpp + 27, r1, r2, r3, r0);  p0 -= 7; LOADROW(r0, p0);  // row k-4-4it
        hpp += 36;
    }

    // ---------------- epilogue ----------------
    const float os0 = ostd[0], os1 = ostd[1], os2 = ostd[2];
    const float os3 = ostd[3], os4 = ostd[4], os5 = ostd[5];
    const float om0 = omean[0], om1 = omean[1], om2 = omean[2];
    const float om3 = omean[3], om4 = omean[4], om5 = omean[5];
    const bool addinit = (k0 == 0);
    float* outp = out + ((long long)b * SEQN + (k0 + kb)) * 6;

#define EPI(j, A0, A1, A2) do {                                               \
    float y0, y1, y2, y3, y4, y5;                                             \
    unpk(A0, y0, y1); unpk(A1, y2, y3); unpk(A2, y4, y5);                     \
    if (addinit) {                                                            \
        int kk = kb + (j);                                                    \
        if (kk < LTAP) {                                                      \
            const float* sp = g_S + kk * 6;                                   \
            y0 += sp[0]; y1 += sp[1]; y2 += sp[2];                            \
            y3 += sp[3]; y4 += sp[4]; y5 += sp[5];                            \
        }                                                                     \
    }                                                                         \
    float* op = outp + (j) * 6;                                               \
    op[0] = fmaf(y0, os0, om0); op[1] = fmaf(y1, os1, om1);                   \
    op[2] = fmaf(y2, os2, om2); op[3] = fmaf(y3, os3, om3);                   \
    op[4] = fmaf(y4, os4, om4); op[5] = fmaf(y5, os5, om5);                   \
} while (0)

    EPI(0, a00, a01, a02);
    EPI(1, a10, a11, a12);
    EPI(2, a20, a21, a22);
    EPI(3, a30, a31, a32);
#undef EPI
}

// ---------------- launch ----------------
extern "C" void kernel_launch(void* const* d_in, const int* in_sizes, int n_in,
                              void* d_out, int out_size) {
    const float* inp   = (const float*)d_in[0];
    const float* A     = (const float*)d_in[1];
    const float* B     = (const float*)d_in[2];
    const float* C     = (const float*)d_in[3];
    const float* D     = (const float*)d_in[4];
    const float* x0    = (const float*)d_in[5];
    const float* imean = (const float*)d_in[6];
    const float* istd  = (const float*)d_in[7];
    const float* omean = (const float*)d_in[8];
    const float* ostd  = (const float*)d_in[9];
    float* out = (float*)d_out;

    k_init<<<64, 256>>>(A, B, x0);

    // doubling: V[1..63] with squarings A^2..A^64 (6 sq), then two A^64 hops
    // s:          m,  j0, nj, dosq
    const int ms[8]  = {1, 2, 4, 8, 16, 32, 64, 64};
    const int j0s[8] = {0, 0, 0, 0,  0,  0,  0, 64};
    const int njs[8] = {1, 2, 4, 8, 16, 32, 64, 64};
    int pi = 0;
    for (int s = 0; s < 8; s++) {
        int dosq = (s < 6) ? 1 : 0;
        int blocks = njs[s] + (dosq ? 128 : 0);
        k_step2<<<blocks, 128>>>(ms[s], j0s[s], njs[s], pi, dosq);
        if (dosq) pi ^= 1;
    }

    k_taps<<<(LTAP * 42 + 255) / 256, 256>>>(C, D);

    dim3 grid(SEQN / TILE, NB);
    k_conv<<<grid, NTHR>>>(inp, imean, istd, omean, ostd, out);
}